// round 11
// baseline (speedup 1.0000x reference)
#include <cuda_runtime.h>
#include <stdint.h>

// FP32 "pulse bits" (B,32 floats of 0.0/1.0, MSB-first) -> FP64 "pulse bits" (B,64).
// fp64: exp11 = 0 (e==0), 2047 (e==255), else e+896; mant52 = m<<29, NaN -> 1<<51, Inf -> 0.
//
// One WARP per (TILES x 8) rows, 2-stage software pipeline:
//   - prefetch next tile's 8 coalesced LDG.32 BEFORE decoding current tile, so
//     reads stay outstanding through the store phase (no phase-boundary bubble).
//   - decode: rows in PAIRS: 2 VOTEs, half-warp row select, one STG.128/lane
//     (lanes 0-15 -> row r, lanes 16-31 -> row r+1; 512B contiguous per store).
// History: R5 180us@53%; R6 batch8 120.4us@81.6%; R7 R=16 neutral;
//          R10 paired stores 119.2us@82.5% issue 35%. Now: hide tile boundaries.

#define RT 8              // rows per tile
#define TILES 4           // tiles per warp
#define THREADS 256

__device__ __forceinline__ void decode_store_pair(
    unsigned va, unsigned vb, bool lowHalf, bool useHi, int nshift,
    uint4* __restrict__ qs)
{
    const unsigned ONE = 0x3F800000u;
    unsigned be = __ballot_sync(0xFFFFFFFFu, va != 0u);
    unsigned bo = __ballot_sync(0xFFFFFFFFu, vb != 0u);
    unsigned u  = __brev(lowHalf ? be : bo);

    unsigned e = (u >> 23) & 0xFFu;
    unsigned m = u & 0x7FFFFFu;
    unsigned exp11  = (e == 0u) ? 0u : (e + 896u);
    unsigned mant23 = m;
    if (e == 255u) { exp11 = 2047u; mant23 = m ? (1u << 22) : 0u; }

    unsigned hi = (u & 0x80000000u) | (exp11 << 20) | (mant23 >> 3);
    unsigned lo = mant23 << 29;

    unsigned src = useHi ? hi : lo;
    unsigned nib = (src >> nshift) & 0xFu;
    uint4 o;
    o.x = (nib & 8u) ? ONE : 0u;
    o.y = (nib & 4u) ? ONE : 0u;
    o.z = (nib & 2u) ? ONE : 0u;
    o.w = (nib & 1u) ? ONE : 0u;
    __stcs(qs, o);
}

__global__ void __launch_bounds__(THREADS)
fp32bits_to_fp64bits_kernel(const unsigned* __restrict__ in,
                            uint4* __restrict__ out,
                            int nrows)
{
    const int lane   = threadIdx.x & 31;
    const int warpId = (int)((blockIdx.x * blockDim.x + threadIdx.x) >> 5);
    const size_t row0 = (size_t)warpId * (RT * TILES);
    if (row0 >= (size_t)nrows) return;

    const int  ll      = lane & 15;
    const bool lowHalf = lane < 16;
    const int  nshift  = 28 - 4 * (ll & 7);
    const bool useHi   = ll < 8;

    const unsigned* p = in  + row0 * 32 + lane;
    uint4*          q = out + row0 * 16 + lane;

    if (row0 + RT * TILES <= (size_t)nrows) {
        unsigned vc[RT], vn[RT];

        // Prime: tile 0 loads
        #pragma unroll
        for (int r = 0; r < RT; r++) vc[r] = __ldcs(p + r * 32);

        #pragma unroll
        for (int t = 0; t < TILES; t++) {
            // Prefetch next tile while current decodes/stores
            if (t + 1 < TILES) {
                const unsigned* pn = p + (size_t)(t + 1) * RT * 32;
                #pragma unroll
                for (int r = 0; r < RT; r++) vn[r] = __ldcs(pn + r * 32);
            }

            uint4* qt = q + (size_t)t * RT * 16;
            #pragma unroll
            for (int r = 0; r < RT; r += 2)
                decode_store_pair(vc[r], vc[r + 1], lowHalf, useHi, nshift,
                                  qt + r * 16);

            #pragma unroll
            for (int r = 0; r < RT; r++) vc[r] = vn[r];
        }
    } else {
        // Tail (not hit for B = 2^21): one row at a time, uint2 stores.
        const unsigned ONE = 0x3F800000u;
        for (int r = 0; r < RT * TILES && row0 + r < (size_t)nrows; r++) {
            unsigned v = __ldcs(p + (size_t)r * 32);
            unsigned u = __brev(__ballot_sync(0xFFFFFFFFu, v != 0u));
            unsigned e = (u >> 23) & 0xFFu;
            unsigned m = u & 0x7FFFFFu;
            unsigned exp11  = (e == 0u) ? 0u : (e + 896u);
            unsigned mant23 = m;
            if (e == 255u) { exp11 = 2047u; mant23 = m ? (1u << 22) : 0u; }
            unsigned hi = (u & 0x80000000u) | (exp11 << 20) | (mant23 >> 3);
            unsigned lo = mant23 << 29;
            unsigned src = (lane < 16) ? hi : lo;
            unsigned two = (src >> (30 - 2 * (lane & 15))) & 3u;
            uint2 o2;
            o2.x = (two & 2u) ? ONE : 0u;
            o2.y = (two & 1u) ? ONE : 0u;
            uint2* qt = (uint2*)(out + (row0 + r) * 16) + lane;
            __stcs(qt, o2);
        }
    }
}

extern "C" void kernel_launch(void* const* d_in, const int* in_sizes, int n_in,
                              void* d_out, int out_size)
{
    const unsigned* in  = (const unsigned*)d_in[0];
    uint4*          out = (uint4*)d_out;
    const int nrows = in_sizes[0] / 32;

    const int rowsPerWarp = RT * TILES;
    const int warps  = (nrows + rowsPerWarp - 1) / rowsPerWarp;
    const int blocks = (warps + (THREADS / 32) - 1) / (THREADS / 32);
    fp32bits_to_fp64bits_kernel<<<blocks, THREADS>>>(in, out, nrows);
}

// round 12
// speedup vs baseline: 1.0206x; 1.0206x over previous
#include <cuda_runtime.h>
#include <stdint.h>

// FP32 "pulse bits" (B,32 floats of 0.0/1.0, MSB-first) -> FP64 "pulse bits" (B,64).
// fp64: exp11 = 0 (e==0), 2047 (e==255), else e+896; mant52 = m<<29, NaN -> 1<<51, Inf -> 0.
//
// One WARP per R rows (R10 design, best = 119.2us @ DRAM 82.5%):
//   Phase 1: R back-to-back coalesced LDG.32 (lane l <- float l of each row).
//   Phase 2: rows in PAIRS: 2 VOTEs, half-warp row select, decode once,
//            one STG.128 per lane (lanes 0-15 -> row r, 16-31 -> row r+1).
// R12 single change: stores __stcs -> __stwt (write-through) to test whether
// L2 write-allocate was throttling DRAM write drain.
// History: R5 180us@53%; R6 120.4@81.6%; R7 R=16 neutral; R10 119.2@82.5%;
//          R11 2-stage pipeline REGRESSED (123.4) -> warp overlap already covers phases.

#define R 8
#define THREADS 256

__global__ void __launch_bounds__(THREADS)
fp32bits_to_fp64bits_kernel(const unsigned* __restrict__ in,
                            uint4* __restrict__ out,   // out as uint4 (4 floats)
                            int nrows)
{
    const int lane   = threadIdx.x & 31;
    const int warpId = (int)((blockIdx.x * blockDim.x + threadIdx.x) >> 5);
    const size_t row0 = (size_t)warpId * R;
    if (row0 >= (size_t)nrows) return;

    const unsigned ONE = 0x3F800000u;          // bits of 1.0f
    const int  ll      = lane & 15;            // uint4 slot within this lane's row
    const bool lowHalf = lane < 16;            // lanes 0-15 -> even row of pair
    const int  nshift  = 28 - 4 * (ll & 7);    // nibble position in hi/lo word
    const bool useHi   = ll < 8;               // slots 0-7 from hi word, 8-15 from lo

    const unsigned* p = in + row0 * 32 + lane;
    uint4* q = out + row0 * 16 + lane;

    if (row0 + R <= (size_t)nrows) {
        // ---- Phase 1: batch all loads (bytes in flight covers DRAM latency) ----
        unsigned v[R];
        #pragma unroll
        for (int r = 0; r < R; r++) v[r] = __ldcs(p + r * 32);

        // ---- Phase 2: decode + store, two rows per iteration ----
        #pragma unroll
        for (int r = 0; r < R; r += 2) {
            unsigned be = __ballot_sync(0xFFFFFFFFu, v[r]     != 0u);
            unsigned bo = __ballot_sync(0xFFFFFFFFu, v[r + 1] != 0u);
            unsigned u  = __brev(lowHalf ? be : bo);   // this half-warp's row word

            unsigned e = (u >> 23) & 0xFFu;
            unsigned m = u & 0x7FFFFFu;

            unsigned exp11  = (e == 0u) ? 0u : (e + 896u);
            unsigned mant23 = m;
            if (e == 255u) {                           // Inf / NaN
                exp11  = 2047u;
                mant23 = m ? (1u << 22) : 0u;          // NaN -> quiet bit only
            }

            unsigned hi = (u & 0x80000000u) | (exp11 << 20) | (mant23 >> 3);
            unsigned lo = mant23 << 29;                // only bits 31..29 may be set

            unsigned src = useHi ? hi : lo;
            unsigned nib = (src >> nshift) & 0xFu;     // this lane's 4 output bits
            uint4 o;
            o.x = (nib & 8u) ? ONE : 0u;
            o.y = (nib & 4u) ? ONE : 0u;
            o.z = (nib & 2u) ? ONE : 0u;
            o.w = (nib & 1u) ? ONE : 0u;
            __stwt(q + r * 16, o);                     // write-through store
        }
    } else {
        // Tail (not hit for B = 2^21): one row at a time, uint2 stores.
        for (int r = 0; r < R && row0 + r < (size_t)nrows; r++) {
            unsigned v = __ldcs(p + r * 32);
            unsigned u = __brev(__ballot_sync(0xFFFFFFFFu, v != 0u));
            unsigned e = (u >> 23) & 0xFFu;
            unsigned m = u & 0x7FFFFFu;
            unsigned exp11  = (e == 0u) ? 0u : (e + 896u);
            unsigned mant23 = m;
            if (e == 255u) { exp11 = 2047u; mant23 = m ? (1u << 22) : 0u; }
            unsigned hi = (u & 0x80000000u) | (exp11 << 20) | (mant23 >> 3);
            unsigned lo = mant23 << 29;
            unsigned src = (lane < 16) ? hi : lo;
            unsigned two = (src >> (30 - 2 * (lane & 15))) & 3u;
            uint2 o2;
            o2.x = (two & 2u) ? ONE : 0u;
            o2.y = (two & 1u) ? ONE : 0u;
            uint2* qt = (uint2*)(out + (row0 + r) * 16) + lane;
            __stwt(qt, o2);
        }
    }
}

extern "C" void kernel_launch(void* const* d_in, const int* in_sizes, int n_in,
                              void* d_out, int out_size)
{
    const unsigned* in  = (const unsigned*)d_in[0];
    uint4*          out = (uint4*)d_out;
    const int nrows = in_sizes[0] / 32;

    const int warps  = (nrows + R - 1) / R;
    const int blocks = (warps + (THREADS / 32) - 1) / (THREADS / 32);
    fp32bits_to_fp64bits_kernel<<<blocks, THREADS>>>(in, out, nrows);
}

// round 15
// speedup vs baseline: 1.0269x; 1.0061x over previous
#include <cuda_runtime.h>
#include <stdint.h>

// FP32 "pulse bits" (B,32 floats of 0.0/1.0, MSB-first) -> FP64 "pulse bits" (B,64).
// fp64: exp11 = 0 (e==0), 2047 (e==255), else e+896; mant52 = m<<29, NaN -> 1<<51, Inf -> 0.
//
// FINAL (R10 design, best measured 119.2us, DRAM 82.5%, 6.5 TB/s effective):
// One WARP per R rows:
//   Phase 1: R back-to-back coalesced LDG.32 (lane l <- float l of each row)
//            -> R*128B in flight per warp covers DRAM latency.
//   Phase 2: rows in PAIRS: 2 VOTEs, half-warp selects its row's packed word,
//            decodes once, stores 4 output words via one STG.128
//            (lanes 0-15 -> row r, lanes 16-31 -> row r+1; 512B contiguous).
// Roofline evidence: traffic minimal (768MB); R7 MLP up = neutral; R11 SW
// pipeline = regression; R12 __stwt = neutral. Residual ~18% DRAM idle is
// read<->write turnaround on the 1:2 mixed stream — not kernel-controllable.

#define R 8
#define THREADS 256

__global__ void __launch_bounds__(THREADS)
fp32bits_to_fp64bits_kernel(const unsigned* __restrict__ in,
                            uint4* __restrict__ out,   // out as uint4 (4 floats)
                            int nrows)
{
    const int lane   = threadIdx.x & 31;
    const int warpId = (int)((blockIdx.x * blockDim.x + threadIdx.x) >> 5);
    const size_t row0 = (size_t)warpId * R;
    if (row0 >= (size_t)nrows) return;

    const unsigned ONE = 0x3F800000u;          // bits of 1.0f
    const int  ll      = lane & 15;            // uint4 slot within this lane's row
    const bool lowHalf = lane < 16;            // lanes 0-15 -> even row of pair
    const int  nshift  = 28 - 4 * (ll & 7);    // nibble position in hi/lo word
    const bool useHi   = ll < 8;               // slots 0-7 from hi word, 8-15 from lo

    const unsigned* p = in + row0 * 32 + lane;
    uint4* q = out + row0 * 16 + lane;

    if (row0 + R <= (size_t)nrows) {
        // ---- Phase 1: batch all loads (bytes in flight covers DRAM latency) ----
        unsigned v[R];
        #pragma unroll
        for (int r = 0; r < R; r++) v[r] = __ldcs(p + r * 32);

        // ---- Phase 2: decode + store, two rows per iteration ----
        #pragma unroll
        for (int r = 0; r < R; r += 2) {
            unsigned be = __ballot_sync(0xFFFFFFFFu, v[r]     != 0u);
            unsigned bo = __ballot_sync(0xFFFFFFFFu, v[r + 1] != 0u);
            unsigned u  = __brev(lowHalf ? be : bo);   // this half-warp's row word

            unsigned e = (u >> 23) & 0xFFu;
            unsigned m = u & 0x7FFFFFu;

            unsigned exp11  = (e == 0u) ? 0u : (e + 896u);
            unsigned mant23 = m;
            if (e == 255u) {                           // Inf / NaN
                exp11  = 2047u;
                mant23 = m ? (1u << 22) : 0u;          // NaN -> quiet bit only
            }

            unsigned hi = (u & 0x80000000u) | (exp11 << 20) | (mant23 >> 3);
            unsigned lo = mant23 << 29;                // only bits 31..29 may be set

            unsigned src = useHi ? hi : lo;
            unsigned nib = (src >> nshift) & 0xFu;     // this lane's 4 output bits
            uint4 o;
            o.x = (nib & 8u) ? ONE : 0u;
            o.y = (nib & 4u) ? ONE : 0u;
            o.z = (nib & 2u) ? ONE : 0u;
            o.w = (nib & 1u) ? ONE : 0u;
            __stcs(q + r * 16, o);                     // rows r (lanes 0-15) / r+1 (16-31)
        }
    } else {
        // Tail (not hit for B = 2^21): one row at a time, uint2 stores.
        for (int r = 0; r < R && row0 + r < (size_t)nrows; r++) {
            unsigned v = __ldcs(p + r * 32);
            unsigned u = __brev(__ballot_sync(0xFFFFFFFFu, v != 0u));
            unsigned e = (u >> 23) & 0xFFu;
            unsigned m = u & 0x7FFFFFu;
            unsigned exp11  = (e == 0u) ? 0u : (e + 896u);
            unsigned mant23 = m;
            if (e == 255u) { exp11 = 2047u; mant23 = m ? (1u << 22) : 0u; }
            unsigned hi = (u & 0x80000000u) | (exp11 << 20) | (mant23 >> 3);
            unsigned lo = mant23 << 29;
            unsigned src = (lane < 16) ? hi : lo;
            unsigned two = (src >> (30 - 2 * (lane & 15))) & 3u;
            uint2 o2;
            o2.x = (two & 2u) ? ONE : 0u;
            o2.y = (two & 1u) ? ONE : 0u;
            uint2* qt = (uint2*)(out + (row0 + r) * 16) + lane;
            __stcs(qt, o2);
        }
    }
}

extern "C" void kernel_launch(void* const* d_in, const int* in_sizes, int n_in,
                              void* d_out, int out_size)
{
    const unsigned* in  = (const unsigned*)d_in[0];
    uint4*          out = (uint4*)d_out;
    const int nrows = in_sizes[0] / 32;

    const int warps  = (nrows + R - 1) / R;
    const int blocks = (warps + (THREADS / 32) - 1) / (THREADS / 32);
    fp32bits_to_fp64bits_kernel<<<blocks, THREADS>>>(in, out, nrows);
}

// round 16
// speedup vs baseline: 1.0343x; 1.0072x over previous
#include <cuda_runtime.h>
#include <stdint.h>

// FP32 "pulse bits" (B,32 floats of 0.0/1.0, MSB-first) -> FP64 "pulse bits" (B,64).
// fp64: exp11 = 0 (e==0), 2047 (e==255), else e+896; mant52 = m<<29, NaN -> 1<<51, Inf -> 0.
//
// FINAL (R10 design; measured 119.2-120.2us across runs, DRAM 82.5%, 6.54 TB/s):
// One WARP per R rows:
//   Phase 1: R back-to-back coalesced LDG.32 (lane l <- float l of each row)
//            -> R*128B in flight per warp covers DRAM latency.
//   Phase 2: rows in PAIRS: 2 VOTEs, half-warp selects its row's packed word,
//            decodes once, stores 4 output words via one STG.128
//            (lanes 0-15 -> row r, lanes 16-31 -> row r+1; 512B contiguous).
// Roofline evidence: traffic minimal (768MB); R7 MLP up = neutral; R11 SW
// pipeline = regression; R12 __stwt = neutral; R15 re-measure = 120.2us.
// Residual ~18% DRAM idle = read<->write turnaround on the 1:2 mixed stream.

#define R 8
#define THREADS 256

__global__ void __launch_bounds__(THREADS)
fp32bits_to_fp64bits_kernel(const unsigned* __restrict__ in,
                            uint4* __restrict__ out,   // out as uint4 (4 floats)
                            int nrows)
{
    const int lane   = threadIdx.x & 31;
    const int warpId = (int)((blockIdx.x * blockDim.x + threadIdx.x) >> 5);
    const size_t row0 = (size_t)warpId * R;
    if (row0 >= (size_t)nrows) return;

    const unsigned ONE = 0x3F800000u;          // bits of 1.0f
    const int  ll      = lane & 15;            // uint4 slot within this lane's row
    const bool lowHalf = lane < 16;            // lanes 0-15 -> even row of pair
    const int  nshift  = 28 - 4 * (ll & 7);    // nibble position in hi/lo word
    const bool useHi   = ll < 8;               // slots 0-7 from hi word, 8-15 from lo

    const unsigned* p = in + row0 * 32 + lane;
    uint4* q = out + row0 * 16 + lane;

    if (row0 + R <= (size_t)nrows) {
        // ---- Phase 1: batch all loads (bytes in flight covers DRAM latency) ----
        unsigned v[R];
        #pragma unroll
        for (int r = 0; r < R; r++) v[r] = __ldcs(p + r * 32);

        // ---- Phase 2: decode + store, two rows per iteration ----
        #pragma unroll
        for (int r = 0; r < R; r += 2) {
            unsigned be = __ballot_sync(0xFFFFFFFFu, v[r]     != 0u);
            unsigned bo = __ballot_sync(0xFFFFFFFFu, v[r + 1] != 0u);
            unsigned u  = __brev(lowHalf ? be : bo);   // this half-warp's row word

            unsigned e = (u >> 23) & 0xFFu;
            unsigned m = u & 0x7FFFFFu;

            unsigned exp11  = (e == 0u) ? 0u : (e + 896u);
            unsigned mant23 = m;
            if (e == 255u) {                           // Inf / NaN
                exp11  = 2047u;
                mant23 = m ? (1u << 22) : 0u;          // NaN -> quiet bit only
            }

            unsigned hi = (u & 0x80000000u) | (exp11 << 20) | (mant23 >> 3);
            unsigned lo = mant23 << 29;                // only bits 31..29 may be set

            unsigned src = useHi ? hi : lo;
            unsigned nib = (src >> nshift) & 0xFu;     // this lane's 4 output bits
            uint4 o;
            o.x = (nib & 8u) ? ONE : 0u;
            o.y = (nib & 4u) ? ONE : 0u;
            o.z = (nib & 2u) ? ONE : 0u;
            o.w = (nib & 1u) ? ONE : 0u;
            __stcs(q + r * 16, o);                     // rows r (lanes 0-15) / r+1 (16-31)
        }
    } else {
        // Tail (not hit for B = 2^21): one row at a time, uint2 stores.
        for (int r = 0; r < R && row0 + r < (size_t)nrows; r++) {
            unsigned v = __ldcs(p + r * 32);
            unsigned u = __brev(__ballot_sync(0xFFFFFFFFu, v != 0u));
            unsigned e = (u >> 23) & 0xFFu;
            unsigned m = u & 0x7FFFFFu;
            unsigned exp11  = (e == 0u) ? 0u : (e + 896u);
            unsigned mant23 = m;
            if (e == 255u) { exp11 = 2047u; mant23 = m ? (1u << 22) : 0u; }
            unsigned hi = (u & 0x80000000u) | (exp11 << 20) | (mant23 >> 3);
            unsigned lo = mant23 << 29;
            unsigned src = (lane < 16) ? hi : lo;
            unsigned two = (src >> (30 - 2 * (lane & 15))) & 3u;
            uint2 o2;
            o2.x = (two & 2u) ? ONE : 0u;
            o2.y = (two & 1u) ? ONE : 0u;
            uint2* qt = (uint2*)(out + (row0 + r) * 16) + lane;
            __stcs(qt, o2);
        }
    }
}

extern "C" void kernel_launch(void* const* d_in, const int* in_sizes, int n_in,
                              void* d_out, int out_size)
{
    const unsigned* in  = (const unsigned*)d_in[0];
    uint4*          out = (uint4*)d_out;
    const int nrows = in_sizes[0] / 32;

    const int warps  = (nrows + R - 1) / R;
    const int blocks = (warps + (THREADS / 32) - 1) / (THREADS / 32);
    fp32bits_to_fp64bits_kernel<<<blocks, THREADS>>>(in, out, nrows);
}